// round 15
// baseline (speedup 1.0000x reference)
#include <cuda_runtime.h>
#include <cuda_fp16.h>
#include <math.h>
#include <stdint.h>

// ---------------- problem constants ----------------
#define TOKENS   32768
#define DIM      384
#define NHEADS   8
#define HD       48
#define HID      1536
#define NWIN     128
#define WTOK     256
#define SCALE    0.14433756729740643f
#define LN_EPS   1e-5f

// ---------------- scratch ----------------
__device__ float  g_h   [(size_t)TOKENS * DIM];      // residual (fp32, window layout)
__device__ __half g_ln  [(size_t)TOKENS * DIM];      // LN out (fp16, k-permuted)
__device__ __half g_qkv [(size_t)TOKENS * 3 * DIM];  // qkv (fp16, natural)
__device__ __half g_att [(size_t)TOKENS * DIM];      // attn out (fp16, k-permuted)
__device__ __half g_hid [(size_t)TOKENS * HID];      // mlp hidden (fp16, k-permuted)
// weights: [N][K] fp16, k-permuted
__device__ __half g_qkvwt[(size_t)2 * 3 * DIM * DIM];
__device__ __half g_projwt[(size_t)2 * DIM * DIM];
__device__ __half g_fc1wt[(size_t)2 * HID * DIM];
__device__ __half g_fc2wt[(size_t)2 * DIM * HID];

// in-32-block k permutation (one LDS.128 per fragment set)
__host__ __device__ __forceinline__ int pos8(int c) {   // c in [0,32)
    int q = c >> 3, r = c & 7;
    return ((r >> 1) << 3) + (q << 1) + (r & 1);
}
__device__ __forceinline__ int permc(int c) {
    return (c & ~31) + pos8(c & 31);
}
// window-layout row -> natural (B,H,W) row
__device__ __forceinline__ int part_src_row(int row) {
    int win = row >> 8, n = row & 255;
    int b = win >> 6, wy = (win >> 3) & 7, wx = win & 7;
    int yi = n >> 4, xi = n & 15;
    return ((b * 128 + wy * 16 + yi) * 128) + wx * 16 + xi;
}

// ---------------- helpers ----------------
__device__ __forceinline__ uint32_t smem_u32(const void* p) {
    uint32_t a;
    asm("{ .reg .u64 t; cvta.to.shared.u64 t, %1; cvt.u32.u64 %0, t; }" : "=r"(a) : "l"(p));
    return a;
}
__device__ __forceinline__ void cp16(uint32_t dst, const void* src) {
    asm volatile("cp.async.cg.shared.global [%0], [%1], 16;" :: "r"(dst), "l"(src));
}
__device__ __forceinline__ void cp_commit() {
    asm volatile("cp.async.commit_group;" ::: "memory");
}
template<int N>
__device__ __forceinline__ void cp_wait() {
    asm volatile("cp.async.wait_group %0;" :: "n"(N) : "memory");
}
__device__ __forceinline__ void mma_f16(float* d, uint32_t a0, uint32_t a1, uint32_t a2,
                                        uint32_t a3, uint32_t b0, uint32_t b1) {
    asm volatile(
        "mma.sync.aligned.m16n8k16.row.col.f32.f16.f16.f32 "
        "{%0,%1,%2,%3}, {%4,%5,%6,%7}, {%8,%9}, {%0,%1,%2,%3};"
        : "+f"(d[0]), "+f"(d[1]), "+f"(d[2]), "+f"(d[3])
        : "r"(a0), "r"(a1), "r"(a2), "r"(a3), "r"(b0), "r"(b1));
}
__device__ __forceinline__ uint32_t pack_h2(float a, float b) {
    __half2 h = __floats2half2_rn(a, b);
    return *reinterpret_cast<uint32_t*>(&h);
}
__device__ __forceinline__ float gelu_f(float x) {
    return 0.5f * x * (1.0f + erff(x * 0.70710678118654752f));
}

// ---------------- layernorm -> fp16 permuted; PART=1 reads x via window map --------
template<int PART>
__global__ void ln_kernel(const float* __restrict__ in, const float* __restrict__ g,
                          const float* __restrict__ b, __half* __restrict__ out) {
    int token = blockIdx.x * 8 + (threadIdx.x >> 5);
    int lane  = threadIdx.x & 31;
    int srow = PART ? part_src_row(token) : token;
    const float* row = in + (size_t)srow * DIM;
    float v[12];
    float s = 0.f;
    #pragma unroll
    for (int i = 0; i < 12; i++) { v[i] = row[lane + i * 32]; s += v[i]; }
    #pragma unroll
    for (int o = 16; o; o >>= 1) s += __shfl_xor_sync(0xffffffffu, s, o);
    float mu = s * (1.f / DIM);
    float vsum = 0.f;
    #pragma unroll
    for (int i = 0; i < 12; i++) { float d = v[i] - mu; vsum += d * d; }
    #pragma unroll
    for (int o = 16; o; o >>= 1) vsum += __shfl_xor_sync(0xffffffffu, vsum, o);
    float rstd = rsqrtf(vsum * (1.f / DIM) + LN_EPS);
    __half* orow = out + (size_t)token * DIM;
    int pp = pos8(lane);
    #pragma unroll
    for (int i = 0; i < 12; i++) {
        int c = lane + i * 32;
        orow[i * 32 + pp] = __float2half((v[i] - mu) * rstd * g[c] + b[c]);
    }
}

// ---------------- fused weight transpose ----------------
__global__ void transpose_all_kernel(const float* __restrict__ qkv_w,
                                     const float* __restrict__ proj_w,
                                     const float* __restrict__ fc1_w,
                                     const float* __restrict__ fc2_w,
                                     __half* __restrict__ qkvwt,
                                     __half* __restrict__ projwt,
                                     __half* __restrict__ fc1wt,
                                     __half* __restrict__ fc2wt) {
    int idx = blockIdx.x;
    int layer = idx / 1728;
    int r = idx % 1728;
    const float* in; __half* out; int K, N, tn, tk;
    if (r < 432) {
        in = qkv_w + (size_t)layer * 384 * 1152;
        out = qkvwt + (size_t)layer * 1152 * 384;
        K = 384; N = 1152; tn = r % 36; tk = r / 36;
    } else if (r < 576) {
        r -= 432;
        in = proj_w + (size_t)layer * 384 * 384;
        out = projwt + (size_t)layer * 384 * 384;
        K = 384; N = 384; tn = r % 12; tk = r / 12;
    } else if (r < 1152) {
        r -= 576;
        in = fc1_w + (size_t)layer * 384 * 1536;
        out = fc1wt + (size_t)layer * 1536 * 384;
        K = 384; N = 1536; tn = r % 48; tk = r / 48;
    } else {
        r -= 1152;
        in = fc2_w + (size_t)layer * 1536 * 384;
        out = fc2wt + (size_t)layer * 384 * 1536;
        K = 1536; N = 384; tn = r % 12; tk = r / 12;
    }
    __shared__ float t[32][33];
    int n0 = tn * 32, k0 = tk * 32;
    int x = threadIdx.x, y = threadIdx.y;
    #pragma unroll
    for (int i = 0; i < 32; i += 8)
        t[y + i][x] = in[(size_t)(k0 + y + i) * N + n0 + x];
    __syncthreads();
    int pp = pos8(x);
    #pragma unroll
    for (int i = 0; i < 32; i += 8)
        out[(size_t)(n0 + y + i) * K + k0 + pp] = __float2half(t[x][y + i]);
}

// ---------------- fp16 mma GEMM: 128x128 tile, BK=32, 6-slot ring, 2 stages/barrier --------
#define STG_BYTES 16384
#define NSTAGE    6
#define GEMM_SMEM (NSTAGE * STG_BYTES)   // 96KB -> 2 CTAs/SM

// MODE 0: out = A@B (fp16, natural)
// MODE 1: out = gelu(A@B + bias) (fp16, permuted)
// MODE 2: out(fp32) += A@B + bias
// MODE 3: d_out[unpartitioned] = Cres + A@B + bias   (final fc2)
// MODE 4: h = x[partition-mapped] + A@B + bias       (layer-0 proj)
template<int MODE>
__global__ void __launch_bounds__(256)
hgemm(const __half* __restrict__ A, const __half* __restrict__ Bt,
      const float* __restrict__ bias, void* __restrict__ Cv,
      const float* __restrict__ Cres,
      int M, int N, int K) {
    extern __shared__ char smem[];
    uint32_t sbase = smem_u32(smem);

    int tid = threadIdx.x;
    int lane = tid & 31, wid = tid >> 5;
    int gid = lane >> 2, tig = lane & 3;
    int wm = wid & 3, wn = wid >> 2;
    int bm = blockIdx.y * 128, bn = blockIdx.x * 128;

    int r0 = tid >> 1;
    int c0 = (tid & 1) * 2;

    int T = K / 32;
    auto issue = [&](int t, int slot) {
        uint32_t ab = sbase + slot * STG_BYTES;
        uint32_t bb = ab + 8192;
        const __half* ag = A  + (size_t)(bm + r0) * K + t * 32 + c0 * 8;
        const __half* bg = Bt + (size_t)(bn + r0) * K + t * 32 + c0 * 8;
        cp16(ab + r0 * 64 + c0 * 16, ag);
        cp16(ab + r0 * 64 + c0 * 16 + 16, ag + 8);
        cp16(bb + r0 * 64 + c0 * 16, bg);
        cp16(bb + r0 * 64 + c0 * 16 + 16, bg + 8);
        cp_commit();
    };

    issue(0, 0); issue(1, 1); issue(2, 2); issue(3, 3);

    float acc[2][8][4];
    #pragma unroll
    for (int mt = 0; mt < 2; mt++)
        #pragma unroll
        for (int nt = 0; nt < 8; nt++)
            #pragma unroll
            for (int r = 0; r < 4; r++) acc[mt][nt][r] = 0.f;

    int I = T >> 1;
    int slot0 = 0;
    int islot = 4;
    for (int i = 0; i < I; i++) {
        if (2 * i + 2 < T) cp_wait<2>();
        else               cp_wait<0>();
        __syncthreads();
        if (2 * i + 4 < T) issue(2 * i + 4, islot);
        if (2 * i + 5 < T) issue(2 * i + 5, islot + 1 == NSTAGE ? 0 : islot + 1);
        islot += 2; if (islot >= NSTAGE) islot -= NSTAGE;

        #pragma unroll
        for (int kk = 0; kk < 2; kk++) {
            int slot = slot0 + kk;
            const char* as = smem + slot * STG_BYTES;
            const char* bs = as + 8192;

            uint4 aa[2][2];
            #pragma unroll
            for (int mt = 0; mt < 2; mt++) {
                int r = wm * 32 + mt * 16 + gid;
                aa[mt][0] = *(const uint4*)(as + r * 64 + tig * 16);
                aa[mt][1] = *(const uint4*)(as + (r + 8) * 64 + tig * 16);
            }
            #pragma unroll
            for (int nt = 0; nt < 8; nt++) {
                int n = wn * 64 + nt * 8 + gid;
                uint4 bb = *(const uint4*)(bs + n * 64 + tig * 16);
                #pragma unroll
                for (int mt = 0; mt < 2; mt++) {
                    mma_f16(acc[mt][nt], aa[mt][0].x, aa[mt][1].x, aa[mt][0].y, aa[mt][1].y,
                            bb.x, bb.y);
                    mma_f16(acc[mt][nt], aa[mt][0].z, aa[mt][1].z, aa[mt][0].w, aa[mt][1].w,
                            bb.z, bb.w);
                }
            }
        }
        slot0 += 2; if (slot0 >= NSTAGE) slot0 -= NSTAGE;
    }

    #pragma unroll
    for (int nt = 0; nt < 8; nt++) {
        int col = bn + wn * 64 + nt * 8 + 2 * tig;
        float2 bv = make_float2(0.f, 0.f);
        if (MODE != 0) { bv.x = bias[col]; bv.y = bias[col + 1]; }
        int pc0 = permc(col);
        #pragma unroll
        for (int mt = 0; mt < 2; mt++) {
            int rr = bm + wm * 32 + mt * 16 + gid;
            #pragma unroll
            for (int h = 0; h < 2; h++) {
                int row = rr + h * 8;
                float v0 = acc[mt][nt][h * 2 + 0];
                float v1 = acc[mt][nt][h * 2 + 1];
                if (MODE == 0) {
                    __half* cp = (__half*)Cv + (size_t)row * N + col;
                    *(__half2*)cp = __floats2half2_rn(v0, v1);
                } else if (MODE == 1) {
                    __half* cp = (__half*)Cv + (size_t)row * N + pc0;
                    *(__half2*)cp = __floats2half2_rn(gelu_f(v0 + bv.x), gelu_f(v1 + bv.y));
                } else if (MODE == 2) {
                    float* cp = (float*)Cv + (size_t)row * N + col;
                    float2 c0_ = *(const float2*)cp;
                    c0_.x += v0 + bv.x;
                    c0_.y += v1 + bv.y;
                    *(float2*)cp = c0_;
                } else if (MODE == 3) {
                    const float* hp = Cres + (size_t)row * N + col;
                    float2 c0_ = *(const float2*)hp;
                    size_t dst = (size_t)part_src_row(row) * 384 + col;
                    *(float2*)((float*)Cv + dst) =
                        make_float2(c0_.x + v0 + bv.x, c0_.y + v1 + bv.y);
                } else {
                    size_t src = (size_t)part_src_row(row) * 384 + col;
                    float2 c0_ = *(const float2*)(Cres + src);
                    float* cp = (float*)Cv + (size_t)row * N + col;
                    *(float2*)cp = make_float2(c0_.x + v0 + bv.x, c0_.y + v1 + bv.y);
                }
            }
        }
    }
}

// ---------------- tensor-core flash attention: half-window CTAs, 2 CTAs/SM ----------------
// grid (NHEADS, NWIN, 2); each CTA: 128 queries (half window), full 256-key window.
// smem: qs[128][64], ks[256][64], vsT[48][264], bs[961]
#define VS_STR    264
#define AT_QS     0
#define AT_KS     16384
#define AT_VS     49152
#define AT_BS     (49152 + 48 * VS_STR * 2)          // 74496
#define ATTN_SMEM (AT_BS + 961 * 4)                  // 78340

__global__ void __launch_bounds__(256, 2)
attn_kernel(const __half* __restrict__ qkv, const float* __restrict__ rpb,
            __half* __restrict__ out) {
    extern __shared__ char smem[];
    __half* qs = (__half*)(smem + AT_QS);
    __half* ks = (__half*)(smem + AT_KS);
    __half* vsT = (__half*)(smem + AT_VS);
    float*  bs = (float*)(smem + AT_BS);

    int head = blockIdx.x;
    int win  = blockIdx.y;
    int half = blockIdx.z;
    int tid  = threadIdx.x;
    int lane = tid & 31, wid = tid >> 5;
    int gid = lane >> 2, tig = lane & 3;
    size_t base = (size_t)win * WTOK;
    int qoff = half * 128;

    // zero pad slots (raw d 48..63 -> slots 4..7 of each 8-group in block1)
    for (int i = tid; i < 384 * 4; i += 256) {
        int g = i & 3, rowid = i >> 2;    // rowid 0..383: 0-127 qs, 128-383 ks
        __half* p = (rowid < 128 ? qs + rowid * 64 : ks + (rowid - 128) * 64)
                    + 32 + g * 8 + 4;
        *(uint2*)p = make_uint2(0u, 0u);
    }
    const __half* qbase = qkv + base * (3 * DIM) + head * HD;
    const __half* kbase = qbase + DIM;
    const __half* vbase = qbase + 2 * DIM;
    // Q: 128 local rows (global row qoff + m)
    for (int idx = tid; idx < 128 * 6; idx += 256) {
        int m = idx / 6, c8 = (idx % 6) * 8;
        uint4 tq = *(const uint4*)(qbase + (size_t)(qoff + m) * (3 * DIM) + c8);
        int blk = c8 & ~31;
        int q2 = ((c8 & 31) >> 3) << 1;
        __half* qp = &qs[m * 64 + blk + q2];
        *(uint32_t*)(qp + 0)  = tq.x;
        *(uint32_t*)(qp + 8)  = tq.y;
        *(uint32_t*)(qp + 16) = tq.z;
        *(uint32_t*)(qp + 24) = tq.w;
    }
    // K: full 256 rows
    for (int idx = tid; idx < 256 * 6; idx += 256) {
        int m = idx / 6, c8 = (idx % 6) * 8;
        uint4 tk = *(const uint4*)(kbase + (size_t)m * (3 * DIM) + c8);
        int blk = c8 & ~31;
        int q2 = ((c8 & 31) >> 3) << 1;
        __half* kp = &ks[m * 64 + blk + q2];
        *(uint32_t*)(kp + 0)  = tk.x;
        *(uint32_t*)(kp + 8)  = tk.y;
        *(uint32_t*)(kp + 16) = tk.z;
        *(uint32_t*)(kp + 24) = tk.w;
    }
    // V: full 256 rows, transposed + key-permuted
    for (int idx = tid; idx < 256 * 6; idx += 256) {
        int m = idx / 6, c8 = (idx % 6) * 8;
        uint4 tv = *(const uint4*)(vbase + (size_t)m * (3 * DIM) + c8);
        int pk = (m & ~31) + pos8(m & 31);
        __half vh[8];
        *(uint4*)vh = tv;
        #pragma unroll
        for (int j = 0; j < 8; j++)
            vsT[(c8 + j) * VS_STR + pk] = vh[j];
    }
    for (int i = tid; i < 961; i += 256)
        bs[i] = __ldg(rpb + i * NHEADS + head);
    __syncthreads();

    int wm = wid;                 // one m16 tile per warp
    int rt[2];
    #pragma unroll
    for (int h = 0; h < 2; h++) {
        int row = qoff + wm * 16 + gid + h * 8;
        rt[h] = (row >> 4) * 31 + (row & 15) + 480;
    }
    float m_[2] = {-1e30f, -1e30f};
    float l_[2] = {0.f, 0.f};
    float oacc[6][4];
    #pragma unroll
    for (int vt = 0; vt < 6; vt++)
        #pragma unroll
        for (int e = 0; e < 4; e++) oacc[vt][e] = 0.f;

    uint4 qf[2][2];   // [ktile][rowhalf]
    #pragma unroll
    for (int kt = 0; kt < 2; kt++) {
        int r = wm * 16 + gid;
        qf[kt][0] = *(const uint4*)&qs[r * 64 + kt * 32 + tig * 8];
        qf[kt][1] = *(const uint4*)&qs[(r + 8) * 64 + kt * 32 + tig * 8];
    }

    for (int kb = 0; kb < WTOK; kb += 32) {
        float sacc[4][4];
        #pragma unroll
        for (int nt = 0; nt < 4; nt++)
            #pragma unroll
            for (int e = 0; e < 4; e++) sacc[nt][e] = 0.f;

        #pragma unroll
        for (int nt = 0; nt < 4; nt++) {
            int kr = kb + nt * 8 + gid;
            uint4 kf0 = *(const uint4*)&ks[kr * 64 + tig * 8];
            uint4 kf1 = *(const uint4*)&ks[kr * 64 + 32 + tig * 8];
            mma_f16(sacc[nt], qf[0][0].x, qf[0][1].x, qf[0][0].y, qf[0][1].y, kf0.x, kf0.y);
            mma_f16(sacc[nt], qf[0][0].z, qf[0][1].z, qf[0][0].w, qf[0][1].w, kf0.z, kf0.w);
            mma_f16(sacc[nt], qf[1][0].x, qf[1][1].x, qf[1][0].y, qf[1][1].y, kf1.x, kf1.y);
            mma_f16(sacc[nt], qf[1][0].z, qf[1][1].z, qf[1][0].w, qf[1][1].w, kf1.z, kf1.w);
        }

        float rmax[2] = {-1e30f, -1e30f};
        #pragma unroll
        for (int nt = 0; nt < 4; nt++)
            #pragma unroll
            for (int e = 0; e < 4; e++) {
                int key = kb + nt * 8 + 2 * tig + (e & 1);
                int ct = (key >> 4) * 31 + (key & 15);
                int h = e >> 1;
                float s = sacc[nt][e] * SCALE + bs[rt[h] - ct];
                sacc[nt][e] = s;
                rmax[h] = fmaxf(rmax[h], s);
            }
        #pragma unroll
        for (int h = 0; h < 2; h++) {
            rmax[h] = fmaxf(rmax[h], __shfl_xor_sync(0xffffffffu, rmax[h], 1));
            rmax[h] = fmaxf(rmax[h], __shfl_xor_sync(0xffffffffu, rmax[h], 2));
        }
        float f_[2];
        #pragma unroll
        for (int h = 0; h < 2; h++) {
            float nm = fmaxf(m_[h], rmax[h]);
            f_[h] = __expf(m_[h] - nm);
            m_[h] = nm;
        }
        float rsum[2] = {0.f, 0.f};
        #pragma unroll
        for (int nt = 0; nt < 4; nt++)
            #pragma unroll
            for (int e = 0; e < 4; e++) {
                int h = e >> 1;
                float p = __expf(sacc[nt][e] - m_[h]);
                sacc[nt][e] = p;
                rsum[h] += p;
            }
        #pragma unroll
        for (int h = 0; h < 2; h++) {
            rsum[h] += __shfl_xor_sync(0xffffffffu, rsum[h], 1);
            rsum[h] += __shfl_xor_sync(0xffffffffu, rsum[h], 2);
            l_[h] = l_[h] * f_[h] + rsum[h];
        }
        #pragma unroll
        for (int vt = 0; vt < 6; vt++)
            #pragma unroll
            for (int e = 0; e < 4; e++)
                oacc[vt][e] *= f_[e >> 1];

        // pack P: two adjacent n8 C tiles = one k16 A fragment (2 fragments for 32 keys)
        uint32_t pa[2][4];
        #pragma unroll
        for (int kk = 0; kk < 2; kk++) {
            pa[kk][0] = pack_h2(sacc[2 * kk][0], sacc[2 * kk][1]);
            pa[kk][1] = pack_h2(sacc[2 * kk][2], sacc[2 * kk][3]);
            pa[kk][2] = pack_h2(sacc[2 * kk + 1][0], sacc[2 * kk + 1][1]);
            pa[kk][3] = pack_h2(sacc[2 * kk + 1][2], sacc[2 * kk + 1][3]);
        }
        #pragma unroll
        for (int vt = 0; vt < 6; vt++) {
            int vrow = vt * 8 + gid;
            uint4 vf = *(const uint4*)&vsT[vrow * VS_STR + kb + tig * 8];
            mma_f16(oacc[vt], pa[0][0], pa[0][1], pa[0][2], pa[0][3], vf.x, vf.y);
            mma_f16(oacc[vt], pa[1][0], pa[1][1], pa[1][2], pa[1][3], vf.z, vf.w);
        }
    }

    #pragma unroll
    for (int h = 0; h < 2; h++) {
        int row = qoff + wm * 16 + gid + h * 8;
        float inv = 1.f / l_[h];
        __half* orow = out + (base + row) * DIM;
        #pragma unroll
        for (int vt = 0; vt < 6; vt++) {
            int d = vt * 8 + 2 * tig;
            int c = head * HD + d;
            int pc = (c & ~31) + pos8(c & 31);
            *(__half2*)&orow[pc] = __floats2half2_rn(
                oacc[vt][h * 2 + 0] * inv, oacc[vt][h * 2 + 1] * inv);
        }
    }
}

// ---------------- host launcher ----------------
extern "C" void kernel_launch(void* const* d_in, const int* in_sizes, int n_in,
                              void* d_out, int out_size) {
    const float* x      = (const float*)d_in[0];
    const float* qkv_w  = (const float*)d_in[1];
    const float* proj_w = (const float*)d_in[2];
    const float* proj_b = (const float*)d_in[3];
    const float* rpb    = (const float*)d_in[4];
    const float* ln1_g  = (const float*)d_in[5];
    const float* ln1_b  = (const float*)d_in[6];
    const float* ln2_g  = (const float*)d_in[7];
    const float* ln2_b  = (const float*)d_in[8];
    const float* fc1_w  = (const float*)d_in[9];
    const float* fc1_b  = (const float*)d_in[10];
    const float* fc2_w  = (const float*)d_in[11];
    const float* fc2_b  = (const float*)d_in[12];

    float *h;
    __half *ln, *qkv, *att, *hid, *qkvwt, *projwt, *fc1wt, *fc2wt;
    cudaGetSymbolAddress((void**)&h,      g_h);
    cudaGetSymbolAddress((void**)&ln,     g_ln);
    cudaGetSymbolAddress((void**)&qkv,    g_qkv);
    cudaGetSymbolAddress((void**)&att,    g_att);
    cudaGetSymbolAddress((void**)&hid,    g_hid);
    cudaGetSymbolAddress((void**)&qkvwt,  g_qkvwt);
    cudaGetSymbolAddress((void**)&projwt, g_projwt);
    cudaGetSymbolAddress((void**)&fc1wt,  g_fc1wt);
    cudaGetSymbolAddress((void**)&fc2wt,  g_fc2wt);

    cudaFuncSetAttribute(attn_kernel, cudaFuncAttributeMaxDynamicSharedMemorySize, ATTN_SMEM);
    cudaFuncSetAttribute(hgemm<0>, cudaFuncAttributeMaxDynamicSharedMemorySize, GEMM_SMEM);
    cudaFuncSetAttribute(hgemm<1>, cudaFuncAttributeMaxDynamicSharedMemorySize, GEMM_SMEM);
    cudaFuncSetAttribute(hgemm<2>, cudaFuncAttributeMaxDynamicSharedMemorySize, GEMM_SMEM);
    cudaFuncSetAttribute(hgemm<3>, cudaFuncAttributeMaxDynamicSharedMemorySize, GEMM_SMEM);
    cudaFuncSetAttribute(hgemm<4>, cudaFuncAttributeMaxDynamicSharedMemorySize, GEMM_SMEM);

    transpose_all_kernel<<<3456, dim3(32, 8)>>>(
        qkv_w, proj_w, fc1_w, fc2_w, qkvwt, projwt, fc1wt, fc2wt);

    for (int i = 0; i < 2; i++) {
        if (i == 0)
            ln_kernel<1><<<TOKENS / 8, 256>>>(x, ln1_g, ln1_b, ln);
        else
            ln_kernel<0><<<TOKENS / 8, 256>>>(h, ln1_g + i * DIM, ln1_b + i * DIM, ln);
        hgemm<0><<<dim3(3 * DIM / 128, TOKENS / 128), 256, GEMM_SMEM>>>(
            ln, qkvwt + (size_t)i * 3 * DIM * DIM, nullptr, qkv, nullptr,
            TOKENS, 3 * DIM, DIM);
        attn_kernel<<<dim3(NHEADS, NWIN, 2), 256, ATTN_SMEM>>>(
            qkv, rpb + (size_t)i * 961 * NHEADS, att);
        if (i == 0) {
            hgemm<4><<<dim3(DIM / 128, TOKENS / 128), 256, GEMM_SMEM>>>(
                att, projwt + (size_t)i * DIM * DIM, proj_b + (size_t)i * DIM, h, x,
                TOKENS, DIM, DIM);
        } else {
            hgemm<2><<<dim3(DIM / 128, TOKENS / 128), 256, GEMM_SMEM>>>(
                att, projwt + (size_t)i * DIM * DIM, proj_b + (size_t)i * DIM, h, nullptr,
                TOKENS, DIM, DIM);
        }
        ln_kernel<0><<<TOKENS / 8, 256>>>(h, ln2_g + i * DIM, ln2_b + i * DIM, ln);
        hgemm<1><<<dim3(HID / 128, TOKENS / 128), 256, GEMM_SMEM>>>(
            ln, fc1wt + (size_t)i * HID * DIM, fc1_b + (size_t)i * HID, hid, nullptr,
            TOKENS, HID, DIM);
        if (i == 0) {
            hgemm<2><<<dim3(DIM / 128, TOKENS / 128), 256, GEMM_SMEM>>>(
                hid, fc2wt + (size_t)i * DIM * HID, fc2_b + (size_t)i * DIM, h, nullptr,
                TOKENS, DIM, HID);
        } else {
            hgemm<3><<<dim3(DIM / 128, TOKENS / 128), 256, GEMM_SMEM>>>(
                hid, fc2wt + (size_t)i * DIM * HID, fc2_b + (size_t)i * DIM,
                (float*)d_out, h, TOKENS, DIM, HID);
        }
    }
}

// round 16
// speedup vs baseline: 1.0389x; 1.0389x over previous
#include <cuda_runtime.h>
#include <cuda_fp16.h>
#include <math.h>
#include <stdint.h>

// ---------------- problem constants ----------------
#define TOKENS   32768
#define DIM      384
#define NHEADS   8
#define HD       48
#define HID      1536
#define NWIN     128
#define WTOK     256
#define SCALE    0.14433756729740643f
#define LN_EPS   1e-5f

// ---------------- scratch ----------------
__device__ float  g_h   [(size_t)TOKENS * DIM];      // residual (fp32, window layout)
__device__ __half g_ln  [(size_t)TOKENS * DIM];      // LN out (fp16, k-permuted)
__device__ __half g_qkv [(size_t)TOKENS * 3 * DIM];  // qkv (fp16, natural)
__device__ __half g_att [(size_t)TOKENS * DIM];      // attn out (fp16, k-permuted)
__device__ __half g_hid [(size_t)TOKENS * HID];      // mlp hidden (fp16, k-permuted)
// weights: [N][K] fp16, k-permuted
__device__ __half g_qkvwt[(size_t)2 * 3 * DIM * DIM];
__device__ __half g_projwt[(size_t)2 * DIM * DIM];
__device__ __half g_fc1wt[(size_t)2 * HID * DIM];
__device__ __half g_fc2wt[(size_t)2 * DIM * HID];

// in-32-block k permutation (one LDS.128 per fragment set)
__host__ __device__ __forceinline__ int pos8(int c) {   // c in [0,32)
    int q = c >> 3, r = c & 7;
    return ((r >> 1) << 3) + (q << 1) + (r & 1);
}
__device__ __forceinline__ int permc(int c) {
    return (c & ~31) + pos8(c & 31);
}
// window-layout row -> natural (B,H,W) row
__device__ __forceinline__ int part_src_row(int row) {
    int win = row >> 8, n = row & 255;
    int b = win >> 6, wy = (win >> 3) & 7, wx = win & 7;
    int yi = n >> 4, xi = n & 15;
    return ((b * 128 + wy * 16 + yi) * 128) + wx * 16 + xi;
}

// ---------------- helpers ----------------
__device__ __forceinline__ uint32_t smem_u32(const void* p) {
    uint32_t a;
    asm("{ .reg .u64 t; cvta.to.shared.u64 t, %1; cvt.u32.u64 %0, t; }" : "=r"(a) : "l"(p));
    return a;
}
__device__ __forceinline__ void cp16(uint32_t dst, const void* src) {
    asm volatile("cp.async.cg.shared.global [%0], [%1], 16;" :: "r"(dst), "l"(src));
}
__device__ __forceinline__ void cp_commit() {
    asm volatile("cp.async.commit_group;" ::: "memory");
}
template<int N>
__device__ __forceinline__ void cp_wait() {
    asm volatile("cp.async.wait_group %0;" :: "n"(N) : "memory");
}
__device__ __forceinline__ void mma_f16(float* d, uint32_t a0, uint32_t a1, uint32_t a2,
                                        uint32_t a3, uint32_t b0, uint32_t b1) {
    asm volatile(
        "mma.sync.aligned.m16n8k16.row.col.f32.f16.f16.f32 "
        "{%0,%1,%2,%3}, {%4,%5,%6,%7}, {%8,%9}, {%0,%1,%2,%3};"
        : "+f"(d[0]), "+f"(d[1]), "+f"(d[2]), "+f"(d[3])
        : "r"(a0), "r"(a1), "r"(a2), "r"(a3), "r"(b0), "r"(b1));
}
__device__ __forceinline__ uint32_t pack_h2(float a, float b) {
    __half2 h = __floats2half2_rn(a, b);
    return *reinterpret_cast<uint32_t*>(&h);
}
__device__ __forceinline__ float gelu_f(float x) {
    return 0.5f * x * (1.0f + erff(x * 0.70710678118654752f));
}

// ---------------- layernorm -> fp16 permuted (vectorized); PART=1 reads x via window map ----
template<int PART>
__global__ void ln_kernel(const float* __restrict__ in, const float* __restrict__ g,
                          const float* __restrict__ b, __half* __restrict__ out) {
    int token = blockIdx.x * 8 + (threadIdx.x >> 5);
    int lane  = threadIdx.x & 31;
    int srow = PART ? part_src_row(token) : token;
    const float4* row = (const float4*)(in + (size_t)srow * DIM);
    float4 v[3];
    float s = 0.f;
    #pragma unroll
    for (int i = 0; i < 3; i++) {
        v[i] = row[lane + i * 32];
        s += v[i].x + v[i].y + v[i].z + v[i].w;
    }
    #pragma unroll
    for (int o = 16; o; o >>= 1) s += __shfl_xor_sync(0xffffffffu, s, o);
    float mu = s * (1.f / DIM);
    float vsum = 0.f;
    #pragma unroll
    for (int i = 0; i < 3; i++) {
        float d0 = v[i].x - mu, d1 = v[i].y - mu, d2 = v[i].z - mu, d3 = v[i].w - mu;
        vsum += d0 * d0 + d1 * d1 + d2 * d2 + d3 * d3;
    }
    #pragma unroll
    for (int o = 16; o; o >>= 1) vsum += __shfl_xor_sync(0xffffffffu, vsum, o);
    float rstd = rsqrtf(vsum * (1.f / DIM) + LN_EPS);

    __half* orow = out + (size_t)token * DIM;
    int a = (lane * 4) & 31;                       // within-32 base (mult of 4)
    int p0 = (((a & 7) >> 1) << 3) + ((a >> 3) << 1);   // pos8(a); pairs at p0, p0+8
    #pragma unroll
    for (int i = 0; i < 3; i++) {
        int c = lane * 4 + i * 128;
        int blk = c & ~31;
        float4 gv = ((const float4*)g)[lane + i * 32];
        float4 bv = ((const float4*)b)[lane + i * 32];
        float n0 = (v[i].x - mu) * rstd * gv.x + bv.x;
        float n1 = (v[i].y - mu) * rstd * gv.y + bv.y;
        float n2 = (v[i].z - mu) * rstd * gv.z + bv.z;
        float n3 = (v[i].w - mu) * rstd * gv.w + bv.w;
        *(__half2*)&orow[blk + p0]     = __floats2half2_rn(n0, n1);
        *(__half2*)&orow[blk + p0 + 8] = __floats2half2_rn(n2, n3);
    }
}

// ---------------- fused weight transpose ----------------
__global__ void transpose_all_kernel(const float* __restrict__ qkv_w,
                                     const float* __restrict__ proj_w,
                                     const float* __restrict__ fc1_w,
                                     const float* __restrict__ fc2_w,
                                     __half* __restrict__ qkvwt,
                                     __half* __restrict__ projwt,
                                     __half* __restrict__ fc1wt,
                                     __half* __restrict__ fc2wt) {
    int idx = blockIdx.x;
    int layer = idx / 1728;
    int r = idx % 1728;
    const float* in; __half* out; int K, N, tn, tk;
    if (r < 432) {
        in = qkv_w + (size_t)layer * 384 * 1152;
        out = qkvwt + (size_t)layer * 1152 * 384;
        K = 384; N = 1152; tn = r % 36; tk = r / 36;
    } else if (r < 576) {
        r -= 432;
        in = proj_w + (size_t)layer * 384 * 384;
        out = projwt + (size_t)layer * 384 * 384;
        K = 384; N = 384; tn = r % 12; tk = r / 12;
    } else if (r < 1152) {
        r -= 576;
        in = fc1_w + (size_t)layer * 384 * 1536;
        out = fc1wt + (size_t)layer * 1536 * 384;
        K = 384; N = 1536; tn = r % 48; tk = r / 48;
    } else {
        r -= 1152;
        in = fc2_w + (size_t)layer * 1536 * 384;
        out = fc2wt + (size_t)layer * 384 * 1536;
        K = 1536; N = 384; tn = r % 12; tk = r / 12;
    }
    __shared__ float t[32][33];
    int n0 = tn * 32, k0 = tk * 32;
    int x = threadIdx.x, y = threadIdx.y;
    #pragma unroll
    for (int i = 0; i < 32; i += 8)
        t[y + i][x] = in[(size_t)(k0 + y + i) * N + n0 + x];
    __syncthreads();
    int pp = pos8(x);
    #pragma unroll
    for (int i = 0; i < 32; i += 8)
        out[(size_t)(n0 + y + i) * K + k0 + pp] = __float2half(t[x][y + i]);
}

// ---------------- fp16 mma GEMM: 128x128 tile, BK=32, 6-slot ring, 2 stages/barrier --------
#define STG_BYTES 16384
#define NSTAGE    6
#define GEMM_SMEM (NSTAGE * STG_BYTES)   // 96KB -> 2 CTAs/SM

// MODE 0: out = A@B (fp16, natural)
// MODE 1: out = gelu(A@B + bias) (fp16, permuted)
// MODE 2: out(fp32) += A@B + bias
// MODE 3: d_out[unpartitioned] = Cres + A@B + bias   (final fc2)
// MODE 4: h = x[partition-mapped] + A@B + bias       (layer-0 proj)
template<int MODE>
__global__ void __launch_bounds__(256)
hgemm(const __half* __restrict__ A, const __half* __restrict__ Bt,
      const float* __restrict__ bias, void* __restrict__ Cv,
      const float* __restrict__ Cres,
      int M, int N, int K) {
    extern __shared__ char smem[];
    uint32_t sbase = smem_u32(smem);

    int tid = threadIdx.x;
    int lane = tid & 31, wid = tid >> 5;
    int gid = lane >> 2, tig = lane & 3;
    int wm = wid & 3, wn = wid >> 2;
    int bm = blockIdx.y * 128, bn = blockIdx.x * 128;

    int r0 = tid >> 1;
    int c0 = (tid & 1) * 2;

    int T = K / 32;
    auto issue = [&](int t, int slot) {
        uint32_t ab = sbase + slot * STG_BYTES;
        uint32_t bb = ab + 8192;
        const __half* ag = A  + (size_t)(bm + r0) * K + t * 32 + c0 * 8;
        const __half* bg = Bt + (size_t)(bn + r0) * K + t * 32 + c0 * 8;
        cp16(ab + r0 * 64 + c0 * 16, ag);
        cp16(ab + r0 * 64 + c0 * 16 + 16, ag + 8);
        cp16(bb + r0 * 64 + c0 * 16, bg);
        cp16(bb + r0 * 64 + c0 * 16 + 16, bg + 8);
        cp_commit();
    };

    issue(0, 0); issue(1, 1); issue(2, 2); issue(3, 3);

    float acc[2][8][4];
    #pragma unroll
    for (int mt = 0; mt < 2; mt++)
        #pragma unroll
        for (int nt = 0; nt < 8; nt++)
            #pragma unroll
            for (int r = 0; r < 4; r++) acc[mt][nt][r] = 0.f;

    int I = T >> 1;
    int slot0 = 0;
    int islot = 4;
    for (int i = 0; i < I; i++) {
        if (2 * i + 2 < T) cp_wait<2>();
        else               cp_wait<0>();
        __syncthreads();
        if (2 * i + 4 < T) issue(2 * i + 4, islot);
        if (2 * i + 5 < T) issue(2 * i + 5, islot + 1 == NSTAGE ? 0 : islot + 1);
        islot += 2; if (islot >= NSTAGE) islot -= NSTAGE;

        #pragma unroll
        for (int kk = 0; kk < 2; kk++) {
            int slot = slot0 + kk;
            const char* as = smem + slot * STG_BYTES;
            const char* bs = as + 8192;

            uint4 aa[2][2];
            #pragma unroll
            for (int mt = 0; mt < 2; mt++) {
                int r = wm * 32 + mt * 16 + gid;
                aa[mt][0] = *(const uint4*)(as + r * 64 + tig * 16);
                aa[mt][1] = *(const uint4*)(as + (r + 8) * 64 + tig * 16);
            }
            #pragma unroll
            for (int nt = 0; nt < 8; nt++) {
                int n = wn * 64 + nt * 8 + gid;
                uint4 bb = *(const uint4*)(bs + n * 64 + tig * 16);
                #pragma unroll
                for (int mt = 0; mt < 2; mt++) {
                    mma_f16(acc[mt][nt], aa[mt][0].x, aa[mt][1].x, aa[mt][0].y, aa[mt][1].y,
                            bb.x, bb.y);
                    mma_f16(acc[mt][nt], aa[mt][0].z, aa[mt][1].z, aa[mt][0].w, aa[mt][1].w,
                            bb.z, bb.w);
                }
            }
        }
        slot0 += 2; if (slot0 >= NSTAGE) slot0 -= NSTAGE;
    }

    #pragma unroll
    for (int nt = 0; nt < 8; nt++) {
        int col = bn + wn * 64 + nt * 8 + 2 * tig;
        float2 bv = make_float2(0.f, 0.f);
        if (MODE != 0) { bv.x = bias[col]; bv.y = bias[col + 1]; }
        int pc0 = permc(col);
        #pragma unroll
        for (int mt = 0; mt < 2; mt++) {
            int rr = bm + wm * 32 + mt * 16 + gid;
            #pragma unroll
            for (int h = 0; h < 2; h++) {
                int row = rr + h * 8;
                float v0 = acc[mt][nt][h * 2 + 0];
                float v1 = acc[mt][nt][h * 2 + 1];
                if (MODE == 0) {
                    __half* cp = (__half*)Cv + (size_t)row * N + col;
                    *(__half2*)cp = __floats2half2_rn(v0, v1);
                } else if (MODE == 1) {
                    __half* cp = (__half*)Cv + (size_t)row * N + pc0;
                    *(__half2*)cp = __floats2half2_rn(gelu_f(v0 + bv.x), gelu_f(v1 + bv.y));
                } else if (MODE == 2) {
                    float* cp = (float*)Cv + (size_t)row * N + col;
                    float2 c0_ = *(const float2*)cp;
                    c0_.x += v0 + bv.x;
                    c0_.y += v1 + bv.y;
                    *(float2*)cp = c0_;
                } else if (MODE == 3) {
                    const float* hp = Cres + (size_t)row * N + col;
                    float2 c0_ = *(const float2*)hp;
                    size_t dst = (size_t)part_src_row(row) * 384 + col;
                    *(float2*)((float*)Cv + dst) =
                        make_float2(c0_.x + v0 + bv.x, c0_.y + v1 + bv.y);
                } else {
                    size_t src = (size_t)part_src_row(row) * 384 + col;
                    float2 c0_ = *(const float2*)(Cres + src);
                    float* cp = (float*)Cv + (size_t)row * N + col;
                    *(float2*)cp = make_float2(c0_.x + v0 + bv.x, c0_.y + v1 + bv.y);
                }
            }
        }
    }
}

// ---------------- tensor-core flash attention (round-14 config: full window per CTA) ------
#define VS_STR    264
#define AT_QS     0
#define AT_KS     32768
#define AT_VS     65536
#define AT_BS     (65536 + 48 * VS_STR * 2)          // 90880
#define ATTN_SMEM (AT_BS + 961 * 4)                  // 94724

__global__ void __launch_bounds__(256)
attn_kernel(const __half* __restrict__ qkv, const float* __restrict__ rpb,
            __half* __restrict__ out) {
    extern __shared__ char smem[];
    __half* qs = (__half*)(smem + AT_QS);
    __half* ks = (__half*)(smem + AT_KS);
    __half* vsT = (__half*)(smem + AT_VS);
    float*  bs = (float*)(smem + AT_BS);

    int head = blockIdx.x;
    int win  = blockIdx.y;
    int tid  = threadIdx.x;
    int lane = tid & 31, wid = tid >> 5;
    int gid = lane >> 2, tig = lane & 3;
    size_t base = (size_t)win * WTOK;

    for (int i = tid; i < 256 * 8; i += 256) {
        int row = i >> 3, g = (i >> 1) & 3, buf = i & 1;
        __half* p = (buf ? ks : qs) + row * 64 + 32 + g * 8 + 4;
        *(uint2*)p = make_uint2(0u, 0u);
    }
    const __half* qbase = qkv + base * (3 * DIM) + head * HD;
    const __half* kbase = qbase + DIM;
    const __half* vbase = qbase + 2 * DIM;
    for (int idx = tid; idx < 256 * 6; idx += 256) {
        int m = idx / 6, c8 = (idx % 6) * 8;
        uint4 tq = *(const uint4*)(qbase + (size_t)m * (3 * DIM) + c8);
        uint4 tk = *(const uint4*)(kbase + (size_t)m * (3 * DIM) + c8);
        uint4 tv = *(const uint4*)(vbase + (size_t)m * (3 * DIM) + c8);
        int blk = c8 & ~31;
        int q2 = ((c8 & 31) >> 3) << 1;
        __half* qp = &qs[m * 64 + blk + q2];
        __half* kp = &ks[m * 64 + blk + q2];
        *(uint32_t*)(qp + 0)  = tq.x;  *(uint32_t*)(kp + 0)  = tk.x;
        *(uint32_t*)(qp + 8)  = tq.y;  *(uint32_t*)(kp + 8)  = tk.y;
        *(uint32_t*)(qp + 16) = tq.z;  *(uint32_t*)(kp + 16) = tk.z;
        *(uint32_t*)(qp + 24) = tq.w;  *(uint32_t*)(kp + 24) = tk.w;
        int pk = (m & ~31) + pos8(m & 31);
        __half vh[8];
        *(uint4*)vh = tv;
        #pragma unroll
        for (int j = 0; j < 8; j++)
            vsT[(c8 + j) * VS_STR + pk] = vh[j];
    }
    for (int i = tid; i < 961; i += 256)
        bs[i] = __ldg(rpb + i * NHEADS + head);
    __syncthreads();

    int wm = wid;
    int rt[4];
    #pragma unroll
    for (int ri = 0; ri < 4; ri++) {
        int row = wm * 32 + (ri >> 1) * 16 + gid + (ri & 1) * 8;
        rt[ri] = (row >> 4) * 31 + (row & 15) + 480;
    }
    float m_[4] = {-1e30f, -1e30f, -1e30f, -1e30f};
    float l_[4] = {0.f, 0.f, 0.f, 0.f};
    float oacc[2][6][4];
    #pragma unroll
    for (int mt = 0; mt < 2; mt++)
        #pragma unroll
        for (int vt = 0; vt < 6; vt++)
            #pragma unroll
            for (int e = 0; e < 4; e++) oacc[mt][vt][e] = 0.f;

    uint4 qf[2][2][2];
    #pragma unroll
    for (int mt = 0; mt < 2; mt++)
        #pragma unroll
        for (int kt = 0; kt < 2; kt++) {
            int r = wm * 32 + mt * 16 + gid;
            qf[mt][kt][0] = *(const uint4*)&qs[r * 64 + kt * 32 + tig * 8];
            qf[mt][kt][1] = *(const uint4*)&qs[(r + 8) * 64 + kt * 32 + tig * 8];
        }

    for (int kb = 0; kb < WTOK; kb += 64) {
        float sacc[2][8][4];
        #pragma unroll
        for (int mt = 0; mt < 2; mt++)
            #pragma unroll
            for (int nt = 0; nt < 8; nt++)
                #pragma unroll
                for (int e = 0; e < 4; e++) sacc[mt][nt][e] = 0.f;

        #pragma unroll
        for (int nt = 0; nt < 8; nt++) {
            int kr = kb + nt * 8 + gid;
            uint4 kf0 = *(const uint4*)&ks[kr * 64 + tig * 8];
            uint4 kf1 = *(const uint4*)&ks[kr * 64 + 32 + tig * 8];
            #pragma unroll
            for (int mt = 0; mt < 2; mt++) {
                mma_f16(sacc[mt][nt], qf[mt][0][0].x, qf[mt][0][1].x,
                        qf[mt][0][0].y, qf[mt][0][1].y, kf0.x, kf0.y);
                mma_f16(sacc[mt][nt], qf[mt][0][0].z, qf[mt][0][1].z,
                        qf[mt][0][0].w, qf[mt][0][1].w, kf0.z, kf0.w);
                mma_f16(sacc[mt][nt], qf[mt][1][0].x, qf[mt][1][1].x,
                        qf[mt][1][0].y, qf[mt][1][1].y, kf1.x, kf1.y);
                mma_f16(sacc[mt][nt], qf[mt][1][0].z, qf[mt][1][1].z,
                        qf[mt][1][0].w, qf[mt][1][1].w, kf1.z, kf1.w);
            }
        }

        float rmax[4] = {-1e30f, -1e30f, -1e30f, -1e30f};
        #pragma unroll
        for (int mt = 0; mt < 2; mt++)
            #pragma unroll
            for (int nt = 0; nt < 8; nt++)
                #pragma unroll
                for (int e = 0; e < 4; e++) {
                    int key = kb + nt * 8 + 2 * tig + (e & 1);
                    int ct = (key >> 4) * 31 + (key & 15);
                    int ri = mt * 2 + (e >> 1);
                    float s = sacc[mt][nt][e] * SCALE + bs[rt[ri] - ct];
                    sacc[mt][nt][e] = s;
                    rmax[ri] = fmaxf(rmax[ri], s);
                }
        #pragma unroll
        for (int ri = 0; ri < 4; ri++) {
            rmax[ri] = fmaxf(rmax[ri], __shfl_xor_sync(0xffffffffu, rmax[ri], 1));
            rmax[ri] = fmaxf(rmax[ri], __shfl_xor_sync(0xffffffffu, rmax[ri], 2));
        }
        float f_[4];
        #pragma unroll
        for (int ri = 0; ri < 4; ri++) {
            float nm = fmaxf(m_[ri], rmax[ri]);
            f_[ri] = __expf(m_[ri] - nm);
            m_[ri] = nm;
        }
        float rsum[4] = {0.f, 0.f, 0.f, 0.f};
        #pragma unroll
        for (int mt = 0; mt < 2; mt++)
            #pragma unroll
            for (int nt = 0; nt < 8; nt++)
                #pragma unroll
                for (int e = 0; e < 4; e++) {
                    int ri = mt * 2 + (e >> 1);
                    float p = __expf(sacc[mt][nt][e] - m_[ri]);
                    sacc[mt][nt][e] = p;
                    rsum[ri] += p;
                }
        #pragma unroll
        for (int ri = 0; ri < 4; ri++) {
            rsum[ri] += __shfl_xor_sync(0xffffffffu, rsum[ri], 1);
            rsum[ri] += __shfl_xor_sync(0xffffffffu, rsum[ri], 2);
            l_[ri] = l_[ri] * f_[ri] + rsum[ri];
        }
        #pragma unroll
        for (int mt = 0; mt < 2; mt++)
            #pragma unroll
            for (int vt = 0; vt < 6; vt++)
                #pragma unroll
                for (int e = 0; e < 4; e++)
                    oacc[mt][vt][e] *= f_[mt * 2 + (e >> 1)];

        uint32_t pa[2][4][4];
        #pragma unroll
        for (int mt = 0; mt < 2; mt++)
            #pragma unroll
            for (int kk = 0; kk < 4; kk++) {
                pa[mt][kk][0] = pack_h2(sacc[mt][2 * kk][0], sacc[mt][2 * kk][1]);
                pa[mt][kk][1] = pack_h2(sacc[mt][2 * kk][2], sacc[mt][2 * kk][3]);
                pa[mt][kk][2] = pack_h2(sacc[mt][2 * kk + 1][0], sacc[mt][2 * kk + 1][1]);
                pa[mt][kk][3] = pack_h2(sacc[mt][2 * kk + 1][2], sacc[mt][2 * kk + 1][3]);
            }
        #pragma unroll
        for (int vt = 0; vt < 6; vt++) {
            int vrow = vt * 8 + gid;
            uint4 vf0 = *(const uint4*)&vsT[vrow * VS_STR + kb + tig * 8];
            uint4 vf1 = *(const uint4*)&vsT[vrow * VS_STR + kb + 32 + tig * 8];
            #pragma unroll
            for (int mt = 0; mt < 2; mt++) {
                mma_f16(oacc[mt][vt], pa[mt][0][0], pa[mt][0][1], pa[mt][0][2], pa[mt][0][3],
                        vf0.x, vf0.y);
                mma_f16(oacc[mt][vt], pa[mt][1][0], pa[mt][1][1], pa[mt][1][2], pa[mt][1][3],
                        vf0.z, vf0.w);
                mma_f16(oacc[mt][vt], pa[mt][2][0], pa[mt][2][1], pa[mt][2][2], pa[mt][2][3],
                        vf1.x, vf1.y);
                mma_f16(oacc[mt][vt], pa[mt][3][0], pa[mt][3][1], pa[mt][3][2], pa[mt][3][3],
                        vf1.z, vf1.w);
            }
        }
    }

    #pragma unroll
    for (int mt = 0; mt < 2; mt++)
        #pragma unroll
        for (int h = 0; h < 2; h++) {
            int row = wm * 32 + mt * 16 + gid + h * 8;
            float inv = 1.f / l_[mt * 2 + h];
            __half* orow = out + (base + row) * DIM;
            #pragma unroll
            for (int vt = 0; vt < 6; vt++) {
                int d = vt * 8 + 2 * tig;
                int c = head * HD + d;
                int pc = (c & ~31) + pos8(c & 31);
                *(__half2*)&orow[pc] = __floats2half2_rn(
                    oacc[mt][vt][h * 2 + 0] * inv, oacc[mt][vt][h * 2 + 1] * inv);
            }
        }
}

// ---------------- host launcher ----------------
extern "C" void kernel_launch(void* const* d_in, const int* in_sizes, int n_in,
                              void* d_out, int out_size) {
    const float* x      = (const float*)d_in[0];
    const float* qkv_w  = (const float*)d_in[1];
    const float* proj_w = (const float*)d_in[2];
    const float* proj_b = (const float*)d_in[3];
    const float* rpb    = (const float*)d_in[4];
    const float* ln1_g  = (const float*)d_in[5];
    const float* ln1_b  = (const float*)d_in[6];
    const float* ln2_g  = (const float*)d_in[7];
    const float* ln2_b  = (const float*)d_in[8];
    const float* fc1_w  = (const float*)d_in[9];
    const float* fc1_b  = (const float*)d_in[10];
    const float* fc2_w  = (const float*)d_in[11];
    const float* fc2_b  = (const float*)d_in[12];

    float *h;
    __half *ln, *qkv, *att, *hid, *qkvwt, *projwt, *fc1wt, *fc2wt;
    cudaGetSymbolAddress((void**)&h,      g_h);
    cudaGetSymbolAddress((void**)&ln,     g_ln);
    cudaGetSymbolAddress((void**)&qkv,    g_qkv);
    cudaGetSymbolAddress((void**)&att,    g_att);
    cudaGetSymbolAddress((void**)&hid,    g_hid);
    cudaGetSymbolAddress((void**)&qkvwt,  g_qkvwt);
    cudaGetSymbolAddress((void**)&projwt, g_projwt);
    cudaGetSymbolAddress((void**)&fc1wt,  g_fc1wt);
    cudaGetSymbolAddress((void**)&fc2wt,  g_fc2wt);

    cudaFuncSetAttribute(attn_kernel, cudaFuncAttributeMaxDynamicSharedMemorySize, ATTN_SMEM);
    cudaFuncSetAttribute(hgemm<0>, cudaFuncAttributeMaxDynamicSharedMemorySize, GEMM_SMEM);
    cudaFuncSetAttribute(hgemm<1>, cudaFuncAttributeMaxDynamicSharedMemorySize, GEMM_SMEM);
    cudaFuncSetAttribute(hgemm<2>, cudaFuncAttributeMaxDynamicSharedMemorySize, GEMM_SMEM);
    cudaFuncSetAttribute(hgemm<3>, cudaFuncAttributeMaxDynamicSharedMemorySize, GEMM_SMEM);
    cudaFuncSetAttribute(hgemm<4>, cudaFuncAttributeMaxDynamicSharedMemorySize, GEMM_SMEM);

    transpose_all_kernel<<<3456, dim3(32, 8)>>>(
        qkv_w, proj_w, fc1_w, fc2_w, qkvwt, projwt, fc1wt, fc2wt);

    for (int i = 0; i < 2; i++) {
        if (i == 0)
            ln_kernel<1><<<TOKENS / 8, 256>>>(x, ln1_g, ln1_b, ln);
        else
            ln_kernel<0><<<TOKENS / 8, 256>>>(h, ln1_g + i * DIM, ln1_b + i * DIM, ln);
        hgemm<0><<<dim3(3 * DIM / 128, TOKENS / 128), 256, GEMM_SMEM>>>(
            ln, qkvwt + (size_t)i * 3 * DIM * DIM, nullptr, qkv, nullptr,
            TOKENS, 3 * DIM, DIM);
        attn_kernel<<<dim3(NHEADS, NWIN), 256, ATTN_SMEM>>>(
            qkv, rpb + (size_t)i * 961 * NHEADS, att);
        if (i == 0) {
            hgemm<4><<<dim3(DIM / 128, TOKENS / 128), 256, GEMM_SMEM>>>(
                att, projwt + (size_t)i * DIM * DIM, proj_b + (size_t)i * DIM, h, x,
                TOKENS, DIM, DIM);
        } else {
            hgemm<2><<<dim3(DIM / 128, TOKENS / 128), 256, GEMM_SMEM>>>(
                att, projwt + (size_t)i * DIM * DIM, proj_b + (size_t)i * DIM, h, nullptr,
                TOKENS, DIM, DIM);
        }
        ln_kernel<0><<<TOKENS / 8, 256>>>(h, ln2_g + i * DIM, ln2_b + i * DIM, ln);
        hgemm<1><<<dim3(HID / 128, TOKENS / 128), 256, GEMM_SMEM>>>(
            ln, fc1wt + (size_t)i * HID * DIM, fc1_b + (size_t)i * HID, hid, nullptr,
            TOKENS, HID, DIM);
        if (i == 0) {
            hgemm<2><<<dim3(DIM / 128, TOKENS / 128), 256, GEMM_SMEM>>>(
                hid, fc2wt + (size_t)i * DIM * HID, fc2_b + (size_t)i * DIM, h, nullptr,
                TOKENS, DIM, HID);
        } else {
            hgemm<3><<<dim3(DIM / 128, TOKENS / 128), 256, GEMM_SMEM>>>(
                hid, fc2wt + (size_t)i * DIM * HID, fc2_b + (size_t)i * DIM,
                (float*)d_out, h, TOKENS, DIM, HID);
        }
    }
}

// round 17
// speedup vs baseline: 1.0391x; 1.0002x over previous
#include <cuda_runtime.h>
#include <cuda_fp16.h>
#include <math.h>
#include <stdint.h>

// ---------------- problem constants ----------------
#define TOKENS   32768
#define DIM      384
#define NHEADS   8
#define HD       48
#define HID      1536
#define NWIN     128
#define WTOK     256
#define SCALE    0.14433756729740643f
#define LN_EPS   1e-5f

// ---------------- scratch ----------------
__device__ float  g_h   [(size_t)TOKENS * DIM];      // residual (fp32, window layout)
__device__ __half g_ln  [(size_t)TOKENS * DIM];      // LN out (fp16, k-permuted)
__device__ __half g_qkv [(size_t)TOKENS * 3 * DIM];  // qkv (fp16, natural)
__device__ __half g_att [(size_t)TOKENS * DIM];      // attn out (fp16, k-permuted)
__device__ __half g_hid [(size_t)TOKENS * HID];      // mlp hidden (fp16, k-permuted)
// weights: [N][K] fp16, k-permuted
__device__ __half g_qkvwt[(size_t)2 * 3 * DIM * DIM];
__device__ __half g_projwt[(size_t)2 * DIM * DIM];
__device__ __half g_fc1wt[(size_t)2 * HID * DIM];
__device__ __half g_fc2wt[(size_t)2 * DIM * HID];

// in-32-block k permutation (one LDS.128 per fragment set)
__host__ __device__ __forceinline__ int pos8(int c) {   // c in [0,32)
    int q = c >> 3, r = c & 7;
    return ((r >> 1) << 3) + (q << 1) + (r & 1);
}
__device__ __forceinline__ int permc(int c) {
    return (c & ~31) + pos8(c & 31);
}
// window-layout row -> natural (B,H,W) row
__device__ __forceinline__ int part_src_row(int row) {
    int win = row >> 8, n = row & 255;
    int b = win >> 6, wy = (win >> 3) & 7, wx = win & 7;
    int yi = n >> 4, xi = n & 15;
    return ((b * 128 + wy * 16 + yi) * 128) + wx * 16 + xi;
}

// ---------------- helpers ----------------
__device__ __forceinline__ uint32_t smem_u32(const void* p) {
    uint32_t a;
    asm("{ .reg .u64 t; cvta.to.shared.u64 t, %1; cvt.u32.u64 %0, t; }" : "=r"(a) : "l"(p));
    return a;
}
__device__ __forceinline__ void cp16(uint32_t dst, const void* src) {
    asm volatile("cp.async.cg.shared.global [%0], [%1], 16;" :: "r"(dst), "l"(src));
}
__device__ __forceinline__ void cp_commit() {
    asm volatile("cp.async.commit_group;" ::: "memory");
}
template<int N>
__device__ __forceinline__ void cp_wait() {
    asm volatile("cp.async.wait_group %0;" :: "n"(N) : "memory");
}
__device__ __forceinline__ void mma_f16(float* d, uint32_t a0, uint32_t a1, uint32_t a2,
                                        uint32_t a3, uint32_t b0, uint32_t b1) {
    asm volatile(
        "mma.sync.aligned.m16n8k16.row.col.f32.f16.f16.f32 "
        "{%0,%1,%2,%3}, {%4,%5,%6,%7}, {%8,%9}, {%0,%1,%2,%3};"
        : "+f"(d[0]), "+f"(d[1]), "+f"(d[2]), "+f"(d[3])
        : "r"(a0), "r"(a1), "r"(a2), "r"(a3), "r"(b0), "r"(b1));
}
__device__ __forceinline__ uint32_t pack_h2(float a, float b) {
    __half2 h = __floats2half2_rn(a, b);
    return *reinterpret_cast<uint32_t*>(&h);
}
__device__ __forceinline__ float gelu_f(float x) {
    return 0.5f * x * (1.0f + erff(x * 0.70710678118654752f));
}

// ---------------- layernorm -> fp16 permuted (vectorized); PART=1 reads x via window map ----
template<int PART>
__global__ void ln_kernel(const float* __restrict__ in, const float* __restrict__ g,
                          const float* __restrict__ b, __half* __restrict__ out) {
    int token = blockIdx.x * 8 + (threadIdx.x >> 5);
    int lane  = threadIdx.x & 31;
    int srow = PART ? part_src_row(token) : token;
    const float4* row = (const float4*)(in + (size_t)srow * DIM);
    float4 v[3];
    float s = 0.f;
    #pragma unroll
    for (int i = 0; i < 3; i++) {
        v[i] = row[lane + i * 32];
        s += v[i].x + v[i].y + v[i].z + v[i].w;
    }
    #pragma unroll
    for (int o = 16; o; o >>= 1) s += __shfl_xor_sync(0xffffffffu, s, o);
    float mu = s * (1.f / DIM);
    float vsum = 0.f;
    #pragma unroll
    for (int i = 0; i < 3; i++) {
        float d0 = v[i].x - mu, d1 = v[i].y - mu, d2 = v[i].z - mu, d3 = v[i].w - mu;
        vsum += d0 * d0 + d1 * d1 + d2 * d2 + d3 * d3;
    }
    #pragma unroll
    for (int o = 16; o; o >>= 1) vsum += __shfl_xor_sync(0xffffffffu, vsum, o);
    float rstd = rsqrtf(vsum * (1.f / DIM) + LN_EPS);

    __half* orow = out + (size_t)token * DIM;
    int a = (lane * 4) & 31;
    int p0 = (((a & 7) >> 1) << 3) + ((a >> 3) << 1);
    #pragma unroll
    for (int i = 0; i < 3; i++) {
        int c = lane * 4 + i * 128;
        int blk = c & ~31;
        float4 gv = ((const float4*)g)[lane + i * 32];
        float4 bv = ((const float4*)b)[lane + i * 32];
        float n0 = (v[i].x - mu) * rstd * gv.x + bv.x;
        float n1 = (v[i].y - mu) * rstd * gv.y + bv.y;
        float n2 = (v[i].z - mu) * rstd * gv.z + bv.z;
        float n3 = (v[i].w - mu) * rstd * gv.w + bv.w;
        *(__half2*)&orow[blk + p0]     = __floats2half2_rn(n0, n1);
        *(__half2*)&orow[blk + p0 + 8] = __floats2half2_rn(n2, n3);
    }
}

// ---------------- fused weight transpose ----------------
__global__ void transpose_all_kernel(const float* __restrict__ qkv_w,
                                     const float* __restrict__ proj_w,
                                     const float* __restrict__ fc1_w,
                                     const float* __restrict__ fc2_w,
                                     __half* __restrict__ qkvwt,
                                     __half* __restrict__ projwt,
                                     __half* __restrict__ fc1wt,
                                     __half* __restrict__ fc2wt) {
    int idx = blockIdx.x;
    int layer = idx / 1728;
    int r = idx % 1728;
    const float* in; __half* out; int K, N, tn, tk;
    if (r < 432) {
        in = qkv_w + (size_t)layer * 384 * 1152;
        out = qkvwt + (size_t)layer * 1152 * 384;
        K = 384; N = 1152; tn = r % 36; tk = r / 36;
    } else if (r < 576) {
        r -= 432;
        in = proj_w + (size_t)layer * 384 * 384;
        out = projwt + (size_t)layer * 384 * 384;
        K = 384; N = 384; tn = r % 12; tk = r / 12;
    } else if (r < 1152) {
        r -= 576;
        in = fc1_w + (size_t)layer * 384 * 1536;
        out = fc1wt + (size_t)layer * 1536 * 384;
        K = 384; N = 1536; tn = r % 48; tk = r / 48;
    } else {
        r -= 1152;
        in = fc2_w + (size_t)layer * 1536 * 384;
        out = fc2wt + (size_t)layer * 384 * 1536;
        K = 1536; N = 384; tn = r % 12; tk = r / 12;
    }
    __shared__ float t[32][33];
    int n0 = tn * 32, k0 = tk * 32;
    int x = threadIdx.x, y = threadIdx.y;
    #pragma unroll
    for (int i = 0; i < 32; i += 8)
        t[y + i][x] = in[(size_t)(k0 + y + i) * N + n0 + x];
    __syncthreads();
    int pp = pos8(x);
    #pragma unroll
    for (int i = 0; i < 32; i += 8)
        out[(size_t)(n0 + y + i) * K + k0 + pp] = __float2half(t[x][y + i]);
}

// ---------------- fp16 mma GEMM: 128x128 tile, BK=32, 6-slot ring, 2 stages/barrier --------
#define STG_BYTES 16384
#define NSTAGE    6
#define GEMM_SMEM (NSTAGE * STG_BYTES)   // 96KB -> 2 CTAs/SM

// MODE 0: out = A@B (fp16, natural)
// MODE 1: out = gelu(A@B + bias) (fp16, permuted)
// MODE 2: out(fp32) += A@B + bias
// MODE 3: d_out[unpartitioned] = Cres + A@B + bias   (final fc2)
// MODE 4: h = x[partition-mapped] + A@B + bias       (layer-0 proj)
template<int MODE>
__global__ void __launch_bounds__(256)
hgemm(const __half* __restrict__ A, const __half* __restrict__ Bt,
      const float* __restrict__ bias, void* __restrict__ Cv,
      const float* __restrict__ Cres,
      int M, int N, int K) {
    extern __shared__ char smem[];
    uint32_t sbase = smem_u32(smem);

    int tid = threadIdx.x;
    int lane = tid & 31, wid = tid >> 5;
    int gid = lane >> 2, tig = lane & 3;
    int wm = wid & 3, wn = wid >> 2;
    int bm = blockIdx.y * 128, bn = blockIdx.x * 128;

    int r0 = tid >> 1;
    int c0 = (tid & 1) * 2;

    int T = K / 32;
    auto issue = [&](int t, int slot) {
        uint32_t ab = sbase + slot * STG_BYTES;
        uint32_t bb = ab + 8192;
        const __half* ag = A  + (size_t)(bm + r0) * K + t * 32 + c0 * 8;
        const __half* bg = Bt + (size_t)(bn + r0) * K + t * 32 + c0 * 8;
        cp16(ab + r0 * 64 + c0 * 16, ag);
        cp16(ab + r0 * 64 + c0 * 16 + 16, ag + 8);
        cp16(bb + r0 * 64 + c0 * 16, bg);
        cp16(bb + r0 * 64 + c0 * 16 + 16, bg + 8);
        cp_commit();
    };

    issue(0, 0); issue(1, 1); issue(2, 2); issue(3, 3);

    float acc[2][8][4];
    #pragma unroll
    for (int mt = 0; mt < 2; mt++)
        #pragma unroll
        for (int nt = 0; nt < 8; nt++)
            #pragma unroll
            for (int r = 0; r < 4; r++) acc[mt][nt][r] = 0.f;

    int I = T >> 1;
    int slot0 = 0;
    int islot = 4;
    for (int i = 0; i < I; i++) {
        if (2 * i + 2 < T) cp_wait<2>();
        else               cp_wait<0>();
        __syncthreads();
        if (2 * i + 4 < T) issue(2 * i + 4, islot);
        if (2 * i + 5 < T) issue(2 * i + 5, islot + 1 == NSTAGE ? 0 : islot + 1);
        islot += 2; if (islot >= NSTAGE) islot -= NSTAGE;

        #pragma unroll
        for (int kk = 0; kk < 2; kk++) {
            int slot = slot0 + kk;
            const char* as = smem + slot * STG_BYTES;
            const char* bs = as + 8192;

            uint4 aa[2][2];
            #pragma unroll
            for (int mt = 0; mt < 2; mt++) {
                int r = wm * 32 + mt * 16 + gid;
                aa[mt][0] = *(const uint4*)(as + r * 64 + tig * 16);
                aa[mt][1] = *(const uint4*)(as + (r + 8) * 64 + tig * 16);
            }
            #pragma unroll
            for (int nt = 0; nt < 8; nt++) {
                int n = wn * 64 + nt * 8 + gid;
                uint4 bb = *(const uint4*)(bs + n * 64 + tig * 16);
                #pragma unroll
                for (int mt = 0; mt < 2; mt++) {
                    mma_f16(acc[mt][nt], aa[mt][0].x, aa[mt][1].x, aa[mt][0].y, aa[mt][1].y,
                            bb.x, bb.y);
                    mma_f16(acc[mt][nt], aa[mt][0].z, aa[mt][1].z, aa[mt][0].w, aa[mt][1].w,
                            bb.z, bb.w);
                }
            }
        }
        slot0 += 2; if (slot0 >= NSTAGE) slot0 -= NSTAGE;
    }

    #pragma unroll
    for (int nt = 0; nt < 8; nt++) {
        int col = bn + wn * 64 + nt * 8 + 2 * tig;
        float2 bv = make_float2(0.f, 0.f);
        if (MODE != 0) { bv.x = bias[col]; bv.y = bias[col + 1]; }
        int pc0 = permc(col);
        #pragma unroll
        for (int mt = 0; mt < 2; mt++) {
            int rr = bm + wm * 32 + mt * 16 + gid;
            #pragma unroll
            for (int h = 0; h < 2; h++) {
                int row = rr + h * 8;
                float v0 = acc[mt][nt][h * 2 + 0];
                float v1 = acc[mt][nt][h * 2 + 1];
                if (MODE == 0) {
                    __half* cp = (__half*)Cv + (size_t)row * N + col;
                    *(__half2*)cp = __floats2half2_rn(v0, v1);
                } else if (MODE == 1) {
                    __half* cp = (__half*)Cv + (size_t)row * N + pc0;
                    *(__half2*)cp = __floats2half2_rn(gelu_f(v0 + bv.x), gelu_f(v1 + bv.y));
                } else if (MODE == 2) {
                    float* cp = (float*)Cv + (size_t)row * N + col;
                    float2 c0_ = *(const float2*)cp;
                    c0_.x += v0 + bv.x;
                    c0_.y += v1 + bv.y;
                    *(float2*)cp = c0_;
                } else if (MODE == 3) {
                    const float* hp = Cres + (size_t)row * N + col;
                    float2 c0_ = *(const float2*)hp;
                    size_t dst = (size_t)part_src_row(row) * 384 + col;
                    *(float2*)((float*)Cv + dst) =
                        make_float2(c0_.x + v0 + bv.x, c0_.y + v1 + bv.y);
                } else {
                    size_t src = (size_t)part_src_row(row) * 384 + col;
                    float2 c0_ = *(const float2*)(Cres + src);
                    float* cp = (float*)Cv + (size_t)row * N + col;
                    *(float2*)cp = make_float2(c0_.x + v0 + bv.x, c0_.y + v1 + bv.y);
                }
            }
        }
    }
}

// ---------------- tensor-core flash attention (full window per CTA, hoisted bias ALU) ------
#define VS_STR    264
#define AT_QS     0
#define AT_KS     32768
#define AT_VS     65536
#define AT_BS     (65536 + 48 * VS_STR * 2)          // 90880
#define ATTN_SMEM (AT_BS + 961 * 4)                  // 94724

__global__ void __launch_bounds__(256)
attn_kernel(const __half* __restrict__ qkv, const float* __restrict__ rpb,
            __half* __restrict__ out) {
    extern __shared__ char smem[];
    __half* qs = (__half*)(smem + AT_QS);
    __half* ks = (__half*)(smem + AT_KS);
    __half* vsT = (__half*)(smem + AT_VS);
    float*  bs = (float*)(smem + AT_BS);

    int head = blockIdx.x;
    int win  = blockIdx.y;
    int tid  = threadIdx.x;
    int lane = tid & 31, wid = tid >> 5;
    int gid = lane >> 2, tig = lane & 3;
    size_t base = (size_t)win * WTOK;

    for (int i = tid; i < 256 * 8; i += 256) {
        int row = i >> 3, g = (i >> 1) & 3, buf = i & 1;
        __half* p = (buf ? ks : qs) + row * 64 + 32 + g * 8 + 4;
        *(uint2*)p = make_uint2(0u, 0u);
    }
    const __half* qbase = qkv + base * (3 * DIM) + head * HD;
    const __half* kbase = qbase + DIM;
    const __half* vbase = qbase + 2 * DIM;
    for (int idx = tid; idx < 256 * 6; idx += 256) {
        int m = idx / 6, c8 = (idx % 6) * 8;
        uint4 tq = *(const uint4*)(qbase + (size_t)m * (3 * DIM) + c8);
        uint4 tk = *(const uint4*)(kbase + (size_t)m * (3 * DIM) + c8);
        uint4 tv = *(const uint4*)(vbase + (size_t)m * (3 * DIM) + c8);
        int blk = c8 & ~31;
        int q2 = ((c8 & 31) >> 3) << 1;
        __half* qp = &qs[m * 64 + blk + q2];
        __half* kp = &ks[m * 64 + blk + q2];
        *(uint32_t*)(qp + 0)  = tq.x;  *(uint32_t*)(kp + 0)  = tk.x;
        *(uint32_t*)(qp + 8)  = tq.y;  *(uint32_t*)(kp + 8)  = tk.y;
        *(uint32_t*)(qp + 16) = tq.z;  *(uint32_t*)(kp + 16) = tk.z;
        *(uint32_t*)(qp + 24) = tq.w;  *(uint32_t*)(kp + 24) = tk.w;
        int pk = (m & ~31) + pos8(m & 31);
        __half vh[8];
        *(uint4*)vh = tv;
        #pragma unroll
        for (int j = 0; j < 8; j++)
            vsT[(c8 + j) * VS_STR + pk] = vh[j];
    }
    for (int i = tid; i < 961; i += 256)
        bs[i] = __ldg(rpb + i * NHEADS + head);
    __syncthreads();

    int wm = wid;
    // rtk[ri] = rowterm + 480 - (kb>>4)*31 (updated incrementally; kb starts at 0)
    int rtk[4];
    #pragma unroll
    for (int ri = 0; ri < 4; ri++) {
        int row = wm * 32 + (ri >> 1) * 16 + gid + (ri & 1) * 8;
        rtk[ri] = (row >> 4) * 31 + (row & 15) + 480;
    }
    float m_[4] = {-1e30f, -1e30f, -1e30f, -1e30f};
    float l_[4] = {0.f, 0.f, 0.f, 0.f};
    float oacc[2][6][4];
    #pragma unroll
    for (int mt = 0; mt < 2; mt++)
        #pragma unroll
        for (int vt = 0; vt < 6; vt++)
            #pragma unroll
            for (int e = 0; e < 4; e++) oacc[mt][vt][e] = 0.f;

    uint4 qf[2][2][2];
    #pragma unroll
    for (int mt = 0; mt < 2; mt++)
        #pragma unroll
        for (int kt = 0; kt < 2; kt++) {
            int r = wm * 32 + mt * 16 + gid;
            qf[mt][kt][0] = *(const uint4*)&qs[r * 64 + kt * 32 + tig * 8];
            qf[mt][kt][1] = *(const uint4*)&qs[(r + 8) * 64 + kt * 32 + tig * 8];
        }

    for (int kb = 0; kb < WTOK; kb += 64) {
        float sacc[2][8][4];
        #pragma unroll
        for (int mt = 0; mt < 2; mt++)
            #pragma unroll
            for (int nt = 0; nt < 8; nt++)
                #pragma unroll
                for (int e = 0; e < 4; e++) sacc[mt][nt][e] = 0.f;

        #pragma unroll
        for (int nt = 0; nt < 8; nt++) {
            int kr = kb + nt * 8 + gid;
            uint4 kf0 = *(const uint4*)&ks[kr * 64 + tig * 8];
            uint4 kf1 = *(const uint4*)&ks[kr * 64 + 32 + tig * 8];
            #pragma unroll
            for (int mt = 0; mt < 2; mt++) {
                mma_f16(sacc[mt][nt], qf[mt][0][0].x, qf[mt][0][1].x,
                        qf[mt][0][0].y, qf[mt][0][1].y, kf0.x, kf0.y);
                mma_f16(sacc[mt][nt], qf[mt][0][0].z, qf[mt][0][1].z,
                        qf[mt][0][0].w, qf[mt][0][1].w, kf0.z, kf0.w);
                mma_f16(sacc[mt][nt], qf[mt][1][0].x, qf[mt][1][1].x,
                        qf[mt][1][0].y, qf[mt][1][1].y, kf1.x, kf1.y);
                mma_f16(sacc[mt][nt], qf[mt][1][0].z, qf[mt][1][1].z,
                        qf[mt][1][0].w, qf[mt][1][1].w, kf1.z, kf1.w);
            }
        }

        // scale + bias + row max (hoisted index math: ct = kbterm + ct0(koff),
        // koff even -> ct0(koff+1) = ct0(koff)+1; kbterm folded into rtk)
        float rmax[4] = {-1e30f, -1e30f, -1e30f, -1e30f};
        #pragma unroll
        for (int nt = 0; nt < 8; nt++) {
            int koff = nt * 8 + 2 * tig;
            int ct0 = (koff >> 4) * 31 + (koff & 15);
            #pragma unroll
            for (int mt = 0; mt < 2; mt++) {
                #pragma unroll
                for (int e = 0; e < 4; e++) {
                    int ri = mt * 2 + (e >> 1);
                    float s = sacc[mt][nt][e] * SCALE
                            + bs[rtk[ri] - ct0 - (e & 1)];
                    sacc[mt][nt][e] = s;
                    rmax[ri] = fmaxf(rmax[ri], s);
                }
            }
        }
        #pragma unroll
        for (int ri = 0; ri < 4; ri++) {
            rmax[ri] = fmaxf(rmax[ri], __shfl_xor_sync(0xffffffffu, rmax[ri], 1));
            rmax[ri] = fmaxf(rmax[ri], __shfl_xor_sync(0xffffffffu, rmax[ri], 2));
        }
        float f_[4];
        #pragma unroll
        for (int ri = 0; ri < 4; ri++) {
            float nm = fmaxf(m_[ri], rmax[ri]);
            f_[ri] = __expf(m_[ri] - nm);
            m_[ri] = nm;
        }
        float rsum[4] = {0.f, 0.f, 0.f, 0.f};
        #pragma unroll
        for (int mt = 0; mt < 2; mt++)
            #pragma unroll
            for (int nt = 0; nt < 8; nt++)
                #pragma unroll
                for (int e = 0; e < 4; e++) {
                    int ri = mt * 2 + (e >> 1);
                    float p = __expf(sacc[mt][nt][e] - m_[ri]);
                    sacc[mt][nt][e] = p;
                    rsum[ri] += p;
                }
        #pragma unroll
        for (int ri = 0; ri < 4; ri++) {
            rsum[ri] += __shfl_xor_sync(0xffffffffu, rsum[ri], 1);
            rsum[ri] += __shfl_xor_sync(0xffffffffu, rsum[ri], 2);
            l_[ri] = l_[ri] * f_[ri] + rsum[ri];
        }
        #pragma unroll
        for (int mt = 0; mt < 2; mt++)
            #pragma unroll
            for (int vt = 0; vt < 6; vt++)
                #pragma unroll
                for (int e = 0; e < 4; e++)
                    oacc[mt][vt][e] *= f_[mt * 2 + (e >> 1)];

        uint32_t pa[2][4][4];
        #pragma unroll
        for (int mt = 0; mt < 2; mt++)
            #pragma unroll
            for (int kk = 0; kk < 4; kk++) {
                pa[mt][kk][0] = pack_h2(sacc[mt][2 * kk][0], sacc[mt][2 * kk][1]);
                pa[mt][kk][1] = pack_h2(sacc[mt][2 * kk][2], sacc[mt][2 * kk][3]);
                pa[mt][kk][2] = pack_h2(sacc[mt][2 * kk + 1][0], sacc[mt][2 * kk + 1][1]);
                pa[mt][kk][3] = pack_h2(sacc[mt][2 * kk + 1][2], sacc[mt][2 * kk + 1][3]);
            }
        #pragma unroll
        for (int vt = 0; vt < 6; vt++) {
            int vrow = vt * 8 + gid;
            uint4 vf0 = *(const uint4*)&vsT[vrow * VS_STR + kb + tig * 8];
            uint4 vf1 = *(const uint4*)&vsT[vrow * VS_STR + kb + 32 + tig * 8];
            #pragma unroll
            for (int mt = 0; mt < 2; mt++) {
                mma_f16(oacc[mt][vt], pa[mt][0][0], pa[mt][0][1], pa[mt][0][2], pa[mt][0][3],
                        vf0.x, vf0.y);
                mma_f16(oacc[mt][vt], pa[mt][1][0], pa[mt][1][1], pa[mt][1][2], pa[mt][1][3],
                        vf0.z, vf0.w);
                mma_f16(oacc[mt][vt], pa[mt][2][0], pa[mt][2][1], pa[mt][2][2], pa[mt][2][3],
                        vf1.x, vf1.y);
                mma_f16(oacc[mt][vt], pa[mt][3][0], pa[mt][3][1], pa[mt][3][2], pa[mt][3][3],
                        vf1.z, vf1.w);
            }
        }
        #pragma unroll
        for (int ri = 0; ri < 4; ri++) rtk[ri] -= 124;   // (64>>4)*31
    }

    #pragma unroll
    for (int mt = 0; mt < 2; mt++)
        #pragma unroll
        for (int h = 0; h < 2; h++) {
            int row = wm * 32 + mt * 16 + gid + h * 8;
            float inv = 1.f / l_[mt * 2 + h];
            __half* orow = out + (base + row) * DIM;
            #pragma unroll
            for (int vt = 0; vt < 6; vt++) {
                int d = vt * 8 + 2 * tig;
                int c = head * HD + d;
                int pc = (c & ~31) + pos8(c & 31);
                *(__half2*)&orow[pc] = __floats2half2_rn(
                    oacc[mt][vt][h * 2 + 0] * inv, oacc[mt][vt][h * 2 + 1] * inv);
            }
        }
}

// ---------------- host launcher ----------------
extern "C" void kernel_launch(void* const* d_in, const int* in_sizes, int n_in,
                              void* d_out, int out_size) {
    const float* x      = (const float*)d_in[0];
    const float* qkv_w  = (const float*)d_in[1];
    const float* proj_w = (const float*)d_in[2];
    const float* proj_b = (const float*)d_in[3];
    const float* rpb    = (const float*)d_in[4];
    const float* ln1_g  = (const float*)d_in[5];
    const float* ln1_b  = (const float*)d_in[6];
    const float* ln2_g  = (const float*)d_in[7];
    const float* ln2_b  = (const float*)d_in[8];
    const float* fc1_w  = (const float*)d_in[9];
    const float* fc1_b  = (const float*)d_in[10];
    const float* fc2_w  = (const float*)d_in[11];
    const float* fc2_b  = (const float*)d_in[12];

    float *h;
    __half *ln, *qkv, *att, *hid, *qkvwt, *projwt, *fc1wt, *fc2wt;
    cudaGetSymbolAddress((void**)&h,      g_h);
    cudaGetSymbolAddress((void**)&ln,     g_ln);
    cudaGetSymbolAddress((void**)&qkv,    g_qkv);
    cudaGetSymbolAddress((void**)&att,    g_att);
    cudaGetSymbolAddress((void**)&hid,    g_hid);
    cudaGetSymbolAddress((void**)&qkvwt,  g_qkvwt);
    cudaGetSymbolAddress((void**)&projwt, g_projwt);
    cudaGetSymbolAddress((void**)&fc1wt,  g_fc1wt);
    cudaGetSymbolAddress((void**)&fc2wt,  g_fc2wt);

    cudaFuncSetAttribute(attn_kernel, cudaFuncAttributeMaxDynamicSharedMemorySize, ATTN_SMEM);
    cudaFuncSetAttribute(hgemm<0>, cudaFuncAttributeMaxDynamicSharedMemorySize, GEMM_SMEM);
    cudaFuncSetAttribute(hgemm<1>, cudaFuncAttributeMaxDynamicSharedMemorySize, GEMM_SMEM);
    cudaFuncSetAttribute(hgemm<2>, cudaFuncAttributeMaxDynamicSharedMemorySize, GEMM_SMEM);
    cudaFuncSetAttribute(hgemm<3>, cudaFuncAttributeMaxDynamicSharedMemorySize, GEMM_SMEM);
    cudaFuncSetAttribute(hgemm<4>, cudaFuncAttributeMaxDynamicSharedMemorySize, GEMM_SMEM);

    transpose_all_kernel<<<3456, dim3(32, 8)>>>(
        qkv_w, proj_w, fc1_w, fc2_w, qkvwt, projwt, fc1wt, fc2wt);

    for (int i = 0; i < 2; i++) {
        if (i == 0)
            ln_kernel<1><<<TOKENS / 8, 256>>>(x, ln1_g, ln1_b, ln);
        else
            ln_kernel<0><<<TOKENS / 8, 256>>>(h, ln1_g + i * DIM, ln1_b + i * DIM, ln);
        hgemm<0><<<dim3(3 * DIM / 128, TOKENS / 128), 256, GEMM_SMEM>>>(
            ln, qkvwt + (size_t)i * 3 * DIM * DIM, nullptr, qkv, nullptr,
            TOKENS, 3 * DIM, DIM);
        attn_kernel<<<dim3(NHEADS, NWIN), 256, ATTN_SMEM>>>(
            qkv, rpb + (size_t)i * 961 * NHEADS, att);
        if (i == 0) {
            hgemm<4><<<dim3(DIM / 128, TOKENS / 128), 256, GEMM_SMEM>>>(
                att, projwt + (size_t)i * DIM * DIM, proj_b + (size_t)i * DIM, h, x,
                TOKENS, DIM, DIM);
        } else {
            hgemm<2><<<dim3(DIM / 128, TOKENS / 128), 256, GEMM_SMEM>>>(
                att, projwt + (size_t)i * DIM * DIM, proj_b + (size_t)i * DIM, h, nullptr,
                TOKENS, DIM, DIM);
        }
        ln_kernel<0><<<TOKENS / 8, 256>>>(h, ln2_g + i * DIM, ln2_b + i * DIM, ln);
        hgemm<1><<<dim3(HID / 128, TOKENS / 128), 256, GEMM_SMEM>>>(
            ln, fc1wt + (size_t)i * HID * DIM, fc1_b + (size_t)i * HID, hid, nullptr,
            TOKENS, HID, DIM);
        if (i == 0) {
            hgemm<2><<<dim3(DIM / 128, TOKENS / 128), 256, GEMM_SMEM>>>(
                hid, fc2wt + (size_t)i * DIM * HID, fc2_b + (size_t)i * DIM, h, nullptr,
                TOKENS, DIM, HID);
        } else {
            hgemm<3><<<dim3(DIM / 128, TOKENS / 128), 256, GEMM_SMEM>>>(
                hid, fc2wt + (size_t)i * DIM * HID, fc2_b + (size_t)i * DIM,
                (float*)d_out, h, TOKENS, DIM, HID);
        }
    }
}